// round 2
// baseline (speedup 1.0000x reference)
#include <cuda_runtime.h>
#include <math.h>

#define NA   8000
#define NRES 2000
#define KNN_K 15
#define NE   (NA*KNN_K)        // 120000
#define NANG 9998
#define EPAD (938*128)         // 120064 padded edge rows
#define APAD (79*128)          // 10112 padded angle rows
#define PPAD (63*128)          // 8064 padded atom rows

typedef unsigned long long ull;

// ------------------------- scratch (static device memory) -------------------
__device__ float g_coords[NA*3];
__device__ float g_vels[NA*3];
__device__ float g_accs[NA*3];
__device__ float g_tf[NA*3];       // raw edge-force sums per atom
__device__ float g_aacc[NA*3];     // raw angle-force sums per atom
__device__ int   g_nbr[NE];
__device__ float g_nd[NE*3];       // norm_diffs per edge
__device__ float g_P[PPAD*128];    // node_f @ dW1[0:24]
__device__ float g_Q[PPAD*128];    // node_f @ dW1[24:48]
__device__ float g_A1[PPAD*128];   // node_f @ aW1[0:24] + ab1
__device__ float g_H1[(size_t)EPAD*128];
__device__ float g_H2[(size_t)EPAD*128];
__device__ float g_G1[APAD*128];
__device__ float g_G2[APAD*128];
__device__ float g_geom[NANG*8];   // ba(3), bc(3) per angle instance

// ------------------------- init / loss --------------------------------------
__global__ void init_kernel(const float* __restrict__ coords,
                            const float* __restrict__ vels,
                            const float* __restrict__ temp) {
    int i = blockIdx.x*blockDim.x + threadIdx.x;
    if (i >= NA*3) return;
    g_coords[i] = coords[i];
    g_vels[i]   = vels[i] * temp[0];
    g_accs[i]   = 0.0f;
}

__global__ void loss_kernel(const float* __restrict__ coords,
                            const float* __restrict__ vels,
                            const float* __restrict__ temp,
                            const float* __restrict__ dtp,
                            float* __restrict__ out_loss) {
    __shared__ float red[256];
    float T = temp[0], dt = dtp[0];
    float s = 0.0f;
    for (int i = threadIdx.x; i < NA*3; i += 256) {
        float c = coords[i];
        float x = ((vels[i]*T)*dt)*3.0f;         // v0 * dt * n_steps
        float r = (c + x) - c;                   // match reference rounding
        s += r*r;
    }
    red[threadIdx.x] = s; __syncthreads();
    for (int o = 128; o > 0; o >>= 1) {
        if (threadIdx.x < o) red[threadIdx.x] += red[threadIdx.x+o];
        __syncthreads();
    }
    if (threadIdx.x == 0) out_loss[0] = sqrtf(red[0] / (float)NA);
}

// ------------------------- integration --------------------------------------
__global__ void pos_update_kernel(const float* __restrict__ dtp) {
    int i = blockIdx.x*blockDim.x + threadIdx.x;
    if (i >= NA*3) return;
    float dt = dtp[0];
    g_coords[i] = g_coords[i] + g_vels[i]*dt + 0.5f*g_accs[i]*dt*dt;
    g_aacc[i] = 0.0f;
}

__global__ void finalize_kernel(const float* __restrict__ masses,
                                const float* __restrict__ dtp) {
    int i = blockIdx.x*blockDim.x + threadIdx.x;
    if (i >= NA) return;
    float m = masses[i], dt = dtp[0];
#pragma unroll
    for (int d = 0; d < 3; ++d) {
        float tf  = g_tf[i*3+d] / 100.0f;
        float acc = tf / m + g_aacc[i*3+d] / (m*100.0f);
        float al  = g_accs[i*3+d];
        g_vels[i*3+d] += 0.5f*(al + acc)*dt;
        g_accs[i*3+d]  = acc;
    }
}

__global__ void writeout_kernel(float* __restrict__ out) {
    int i = blockIdx.x*blockDim.x + threadIdx.x;
    if (i < NA*3) out[i] = g_coords[i];
}

// ------------------------- KNN ----------------------------------------------
// 8 queries per block (1 warp each). Stream coords through smem in 1024-atom
// chunks. Per-lane sorted top-16 of keys (d2_bits<<32)|idx -> exact top_k
// semantics incl. tie-break toward lower index. Warp merge: 16 rounds of
// warp-min over per-lane sorted lists.
__global__ void knn_kernel() {
    __shared__ float4 chunk[1024];            // 16 KB
    __shared__ ull    lists[8][32][16];       // 32 KB
    int tid  = threadIdx.x;
    int widx = tid >> 5, lane = tid & 31;
    int q = blockIdx.x*8 + widx;              // always < NA (grid=1000)
    float qx = g_coords[q*3+0], qy = g_coords[q*3+1], qz = g_coords[q*3+2];

    ull best[16];
#pragma unroll
    for (int t = 0; t < 16; ++t) best[t] = ~0ull;

    for (int base = 0; base < NA; base += 1024) {
        int n = min(1024, NA - base);
        __syncthreads();
        for (int t = tid; t < n; t += 256)
            chunk[t] = make_float4(g_coords[(base+t)*3+0],
                                   g_coords[(base+t)*3+1],
                                   g_coords[(base+t)*3+2], 0.0f);
        __syncthreads();
        for (int c = lane; c < n; c += 32) {
            float4 p = chunk[c];
            float dx = qx - p.x, dy = qy - p.y, dz = qz - p.z;
            float d2 = dx*dx + dy*dy + dz*dz;
            ull key = ((ull)__float_as_uint(d2) << 32) | (unsigned)(base + c);
            if (key < best[15]) {
                best[15] = key;
#pragma unroll
                for (int t = 15; t > 0; --t) {   // one bubble pass re-sorts
                    ull a = best[t-1], b = best[t];
                    best[t-1] = (a < b) ? a : b;
                    best[t]   = (a < b) ? b : a;
                }
            }
        }
    }

    ull* ml = &lists[widx][lane][0];
#pragma unroll
    for (int t = 0; t < 16; ++t) ml[t] = best[t];

    int p = 0;
#pragma unroll 1
    for (int r = 0; r < 16; ++r) {
        ull cand = (p < 16) ? ml[p] : ~0ull;
        ull m = cand;
#pragma unroll
        for (int o = 16; o > 0; o >>= 1) {
            ull other = __shfl_xor_sync(0xffffffffu, m, o);
            m = (m < other) ? m : other;
        }
        if (cand == m) p++;                     // unique keys -> one owner
        if (lane == 0 && r > 0)
            g_nbr[q*KNN_K + (r-1)] = (int)(unsigned)(m & 0xffffffffull);
        // r==0 is self (d2 == 0)
    }
}

// ------------------------- edge layer 1 (gather) -----------------------------
__global__ void edge_h1_kernel(const float* __restrict__ dW1,
                               const float* __restrict__ db1) {
    int widx = threadIdx.x >> 5, lane = threadIdx.x & 31;
    int e = blockIdx.x*8 + widx;
    if (e >= NE) return;
    int i = e / KNN_K;
    int j = g_nbr[e];
    float dx = g_coords[i*3+0] - g_coords[j*3+0];
    float dy = g_coords[i*3+1] - g_coords[j*3+1];
    float dz = g_coords[i*3+2] - g_coords[j*3+2];
    float d2 = dx*dx + dy*dy + dz*dz;
    float dist = sqrtf(d2);
    float inv = 1.0f / fmaxf(dist, 0.01f);
    if (lane == 0) {
        g_nd[e*3+0] = dx*inv; g_nd[e*3+1] = dy*inv; g_nd[e*3+2] = dz*inv;
    }
    float seq = fminf(fabsf((float)(i >> 2) - (float)(j >> 2)) / 5.0f, 1.0f);

    int n0 = lane*4;
    float4 pp = *(const float4*)&g_P[i*128 + n0];
    float4 qq = *(const float4*)&g_Q[j*128 + n0];
    float4 w48 = *(const float4*)&dW1[48*128 + n0];
    float4 w49 = *(const float4*)&dW1[49*128 + n0];
    float4 b   = *(const float4*)&db1[n0];
    float4 h;
    h.x = tanhf(pp.x + qq.x + dist*w48.x + seq*w49.x + b.x);
    h.y = tanhf(pp.y + qq.y + dist*w48.y + seq*w49.y + b.y);
    h.z = tanhf(pp.z + qq.z + dist*w48.z + seq*w49.z + b.z);
    h.w = tanhf(pp.w + qq.w + dist*w48.w + seq*w49.w + b.w);
    *(float4*)&g_H1[(size_t)e*128 + n0] = h;
}

// ------------------------- generic 128-wide GEMM (+bias,+tanh) ---------------
// C[M,128] = f(A[M,K] @ W[K,128] + b).  fuse: 0 none, 1 +bias, 2 +bias+tanh.
// BM=128, BN=128, BK=16, 256 threads, 8x8 per thread.
__global__ void gemm_tanh_kernel(const float* __restrict__ A,
                                 const float* __restrict__ W,
                                 const float* __restrict__ bias,
                                 float* __restrict__ C,
                                 int M, int K, int fuse) {
    __shared__ float Ast[16][128];   // [k][m]
    __shared__ float Ws [16][128];   // [k][n]
    int tid = threadIdx.x;
    int tm = tid >> 4, tn = tid & 15;
    int bm = blockIdx.x * 128;

    float acc[8][8];
#pragma unroll
    for (int i = 0; i < 8; ++i)
#pragma unroll
        for (int j = 0; j < 8; ++j) acc[i][j] = 0.0f;

    int arow = tid >> 1;               // 0..127
    int acol = (tid & 1) * 8;          // 0 or 8
    int wrow = tid >> 4;               // 0..15
    int wcol = (tid & 15) * 8;

    for (int kk = 0; kk < K; kk += 16) {
        // A tile (transposed store)
        {
            int grow = bm + arow;
            float4 v0 = make_float4(0,0,0,0), v1 = make_float4(0,0,0,0);
            if (grow < M && (kk + acol) < K) {
                const float* ap = A + (size_t)grow*K + kk + acol;
                v0 = *(const float4*)ap;
                v1 = *(const float4*)(ap + 4);
            }
            Ast[acol+0][arow] = v0.x; Ast[acol+1][arow] = v0.y;
            Ast[acol+2][arow] = v0.z; Ast[acol+3][arow] = v0.w;
            Ast[acol+4][arow] = v1.x; Ast[acol+5][arow] = v1.y;
            Ast[acol+6][arow] = v1.z; Ast[acol+7][arow] = v1.w;
        }
        // W tile
        {
            int gk = kk + wrow;
            float4 v0 = make_float4(0,0,0,0), v1 = make_float4(0,0,0,0);
            if (gk < K) {
                const float* wp = W + (size_t)gk*128 + wcol;
                v0 = *(const float4*)wp;
                v1 = *(const float4*)(wp + 4);
            }
            *(float4*)&Ws[wrow][wcol]   = v0;
            *(float4*)&Ws[wrow][wcol+4] = v1;
        }
        __syncthreads();
#pragma unroll
        for (int k2 = 0; k2 < 16; ++k2) {
            float4 a0 = *(const float4*)&Ast[k2][tm*8];
            float4 a1 = *(const float4*)&Ast[k2][tm*8+4];
            float4 w0 = *(const float4*)&Ws[k2][tn*8];
            float4 w1 = *(const float4*)&Ws[k2][tn*8+4];
            float av[8] = {a0.x,a0.y,a0.z,a0.w,a1.x,a1.y,a1.z,a1.w};
            float wv[8] = {w0.x,w0.y,w0.z,w0.w,w1.x,w1.y,w1.z,w1.w};
#pragma unroll
            for (int i = 0; i < 8; ++i)
#pragma unroll
                for (int j = 0; j < 8; ++j)
                    acc[i][j] += av[i]*wv[j];
        }
        __syncthreads();
    }
    // epilogue
    float bv[8];
    if (fuse >= 1) {
        float4 b0 = *(const float4*)&bias[tn*8];
        float4 b1 = *(const float4*)&bias[tn*8+4];
        bv[0]=b0.x; bv[1]=b0.y; bv[2]=b0.z; bv[3]=b0.w;
        bv[4]=b1.x; bv[5]=b1.y; bv[6]=b1.z; bv[7]=b1.w;
    }
#pragma unroll
    for (int i = 0; i < 8; ++i) {
        int m = bm + tm*8 + i;
        if (m < M) {
            float o[8];
#pragma unroll
            for (int j = 0; j < 8; ++j) {
                float v = acc[i][j];
                if (fuse >= 1) v += bv[j];
                if (fuse == 2) v = tanhf(v);
                o[j] = v;
            }
            *(float4*)&C[(size_t)m*128 + tn*8]     = make_float4(o[0],o[1],o[2],o[3]);
            *(float4*)&C[(size_t)m*128 + tn*8 + 4] = make_float4(o[4],o[5],o[6],o[7]);
        }
    }
}

// ------------------------- edge output + per-atom force sum ------------------
__global__ void atom_force_kernel(const float* __restrict__ dW4,
                                  const float* __restrict__ db4) {
    int widx = threadIdx.x >> 5, lane = threadIdx.x & 31;
    int a = blockIdx.x*8 + widx;               // grid=1000 -> a<8000
    float4 wv = *(const float4*)&dW4[lane*4];
    float b4 = db4[0];
    float fx = 0, fy = 0, fz = 0;
#pragma unroll 1
    for (int k = 0; k < KNN_K; ++k) {
        int e = a*KNN_K + k;
        float4 h = *(const float4*)&g_H1[(size_t)e*128 + lane*4];
        float s = h.x*wv.x + h.y*wv.y + h.z*wv.z + h.w*wv.w;
#pragma unroll
        for (int o = 16; o > 0; o >>= 1) s += __shfl_xor_sync(0xffffffffu, s, o);
        s += b4;
        if (lane == 0) {
            fx += s * g_nd[e*3+0];
            fy += s * g_nd[e*3+1];
            fz += s * g_nd[e*3+2];
        }
    }
    if (lane == 0) { g_tf[a*3+0] = fx; g_tf[a*3+1] = fy; g_tf[a*3+2] = fz; }
}

// ------------------------- angles --------------------------------------------
struct AngleInfo { int u1, u2, u3, ct; };
__device__ __forceinline__ AngleInfo angle_info(int inst) {
    AngleInfo ai; int r;
    if (inst < 2000)      { r = inst;       ai.u1=4*r;   ai.u2=4*r+1; ai.u3=4*r+2; ai.ct=4*r+1; }
    else if (inst < 3999) { r = inst-2000;  ai.u1=4*r+1; ai.u2=4*r+2; ai.u3=4*r+4; ai.ct=4*r+2; }
    else if (inst < 5998) { r = inst-3999;  ai.u1=4*r+2; ai.u2=4*r+4; ai.u3=4*r+5; ai.ct=4*r+4; }
    else if (inst < 7998) { r = inst-5998;  ai.u1=4*r;   ai.u2=4*r+1; ai.u3=4*r+3; ai.ct=4*r+1; }
    else                  { r = inst-7998;  ai.u1=4*r+2; ai.u2=4*r+1; ai.u3=4*r+3; ai.ct=4*r+1; }
    return ai;
}

__global__ void angle_geom_kernel(const float* __restrict__ aW1) {
    int widx = threadIdx.x >> 5, lane = threadIdx.x & 31;
    int inst = blockIdx.x*8 + widx;
    if (inst >= NANG) return;
    AngleInfo ai = angle_info(inst);
    float bax = g_coords[ai.u1*3+0] - g_coords[ai.u2*3+0];
    float bay = g_coords[ai.u1*3+1] - g_coords[ai.u2*3+1];
    float baz = g_coords[ai.u1*3+2] - g_coords[ai.u2*3+2];
    float bcx = g_coords[ai.u3*3+0] - g_coords[ai.u2*3+0];
    float bcy = g_coords[ai.u3*3+1] - g_coords[ai.u2*3+1];
    float bcz = g_coords[ai.u3*3+2] - g_coords[ai.u2*3+2];
    float ba_n = sqrtf(bax*bax + bay*bay + baz*baz);
    float bc_n = sqrtf(bcx*bcx + bcy*bcy + bcz*bcz);
    float cosang = (bax*bcx + bay*bcy + baz*bcz) / (ba_n * bc_n);
    cosang = fminf(fmaxf(cosang, -1.0f + 1e-6f), 1.0f - 1e-6f);
    float ang = acosf(cosang);
    if (lane == 0) {
        g_geom[inst*8+0]=bax; g_geom[inst*8+1]=bay; g_geom[inst*8+2]=baz;
        g_geom[inst*8+3]=bcx; g_geom[inst*8+4]=bcy; g_geom[inst*8+5]=bcz;
    }
    int n0 = lane*4;
    float4 a1 = *(const float4*)&g_A1[ai.ct*128 + n0];
    float4 w  = *(const float4*)&aW1[24*128 + n0];
    float4 h;
    h.x = tanhf(a1.x + ang*w.x);
    h.y = tanhf(a1.y + ang*w.y);
    h.z = tanhf(a1.z + ang*w.z);
    h.w = tanhf(a1.w + ang*w.w);
    *(float4*)&g_G1[inst*128 + n0] = h;
}

__global__ void angle_force_kernel(const float* __restrict__ aW3,
                                   const float* __restrict__ ab3) {
    int widx = threadIdx.x >> 5, lane = threadIdx.x & 31;
    int inst = blockIdx.x*8 + widx;
    if (inst >= NANG) return;
    AngleInfo ai = angle_info(inst);
    float4 g = *(const float4*)&g_G2[inst*128 + lane*4];
    float4 w = *(const float4*)&aW3[lane*4];
    float s = g.x*w.x + g.y*w.y + g.z*w.z + g.w*w.w;
#pragma unroll
    for (int o = 16; o > 0; o >>= 1) s += __shfl_xor_sync(0xffffffffu, s, o);
    float af = s + ab3[0];
    if (lane == 0) {
        float bax=g_geom[inst*8+0], bay=g_geom[inst*8+1], baz=g_geom[inst*8+2];
        float bcx=g_geom[inst*8+3], bcy=g_geom[inst*8+4], bcz=g_geom[inst*8+5];
        float ba_n = sqrtf(bax*bax + bay*bay + baz*baz);
        float bc_n = sqrtf(bcx*bcx + bcy*bcy + bcz*bcz);
        // cross(ba, bc)
        float crx = bay*bcz - baz*bcy;
        float cry = baz*bcx - bax*bcz;
        float crz = bax*bcy - bay*bcx;
        // v1 = cross(ba, cr)
        float v1x = bay*crz - baz*cry;
        float v1y = baz*crx - bax*crz;
        float v1z = bax*cry - bay*crx;
        float n1 = fmaxf(sqrtf(v1x*v1x + v1y*v1y + v1z*v1z), 1e-12f);
        // v2 = cross(-bc, cr)
        float v2x = -(bcy*crz - bcz*cry);
        float v2y = -(bcz*crx - bcx*crz);
        float v2z = -(bcx*cry - bcy*crx);
        float n2 = fmaxf(sqrtf(v2x*v2x + v2y*v2y + v2z*v2z), 1e-12f);
        float fax = af*(v1x/n1)/ba_n, fay = af*(v1y/n1)/ba_n, faz = af*(v1z/n1)/ba_n;
        float fcx = af*(v2x/n2)/bc_n, fcy = af*(v2y/n2)/bc_n, fcz = af*(v2z/n2)/bc_n;
        float fbx = -fax - fcx, fby = -fay - fcy, fbz = -faz - fcz;
        atomicAdd(&g_aacc[ai.u1*3+0], fax);
        atomicAdd(&g_aacc[ai.u1*3+1], fay);
        atomicAdd(&g_aacc[ai.u1*3+2], faz);
        atomicAdd(&g_aacc[ai.u2*3+0], fbx);
        atomicAdd(&g_aacc[ai.u2*3+1], fby);
        atomicAdd(&g_aacc[ai.u2*3+2], fbz);
        atomicAdd(&g_aacc[ai.u3*3+0], fcx);
        atomicAdd(&g_aacc[ai.u3*3+1], fcy);
        atomicAdd(&g_aacc[ai.u3*3+2], fcz);
    }
}

// ------------------------- host launcher -------------------------------------
extern "C" void kernel_launch(void* const* d_in, const int* in_sizes, int n_in,
                              void* d_out, int out_size) {
    const float* coords = (const float*)d_in[0];
    const float* node_f = (const float*)d_in[1];
    const float* masses = (const float*)d_in[3];
    const float* vels   = (const float*)d_in[4];
    const float* dW1 = (const float*)d_in[5];
    const float* db1 = (const float*)d_in[6];
    const float* dW2 = (const float*)d_in[7];
    const float* db2 = (const float*)d_in[8];
    const float* dW3 = (const float*)d_in[9];
    const float* db3 = (const float*)d_in[10];
    const float* dW4 = (const float*)d_in[11];
    const float* db4 = (const float*)d_in[12];
    const float* aW1 = (const float*)d_in[13];
    const float* ab1 = (const float*)d_in[14];
    const float* aW2 = (const float*)d_in[15];
    const float* ab2 = (const float*)d_in[16];
    const float* aW3 = (const float*)d_in[17];
    const float* ab3 = (const float*)d_in[18];
    const float* dtp  = (const float*)d_in[20];
    const float* temp = (const float*)d_in[21];
    float* out = (float*)d_out;

    float *pP, *pQ, *pA1, *pH1, *pH2, *pG1, *pG2;
    cudaGetSymbolAddress((void**)&pP,  g_P);
    cudaGetSymbolAddress((void**)&pQ,  g_Q);
    cudaGetSymbolAddress((void**)&pA1, g_A1);
    cudaGetSymbolAddress((void**)&pH1, g_H1);
    cudaGetSymbolAddress((void**)&pH2, g_H2);
    cudaGetSymbolAddress((void**)&pG1, g_G1);
    cudaGetSymbolAddress((void**)&pG2, g_G2);

    init_kernel<<<(NA*3 + 255)/256, 256>>>(coords, vels, temp);
    loss_kernel<<<1, 256>>>(coords, vels, temp, dtp, out + (out_size - 1));

    // static precomputes (node_f is constant across steps)
    gemm_tanh_kernel<<<63, 256>>>(node_f, dW1,           nullptr, pP,  NA, 24, 0);
    gemm_tanh_kernel<<<63, 256>>>(node_f, dW1 + 24*128,  nullptr, pQ,  NA, 24, 0);
    gemm_tanh_kernel<<<63, 256>>>(node_f, aW1,           ab1,     pA1, NA, 24, 1);

    for (int s = 0; s < 3; ++s) {
        pos_update_kernel<<<94, 256>>>(dtp);
        if (s == 2) break;   // step 3's vels/accs are discarded by the reference

        knn_kernel<<<1000, 256>>>();
        edge_h1_kernel<<<15000, 256>>>(dW1, db1);
        gemm_tanh_kernel<<<938, 256>>>(pH1, dW2, db2, pH2, NE, 128, 2);
        gemm_tanh_kernel<<<938, 256>>>(pH2, dW3, db3, pH1, NE, 128, 2);
        atom_force_kernel<<<1000, 256>>>(dW4, db4);

        angle_geom_kernel<<<1250, 256>>>(aW1);
        gemm_tanh_kernel<<<79, 256>>>(pG1, aW2, ab2, pG2, NANG, 128, 2);
        angle_force_kernel<<<1250, 256>>>(aW3, ab3);

        finalize_kernel<<<(NA + 255)/256, 256>>>(masses, dtp);
    }

    writeout_kernel<<<94, 256>>>(out);
}

// round 5
// speedup vs baseline: 1.3396x; 1.3396x over previous
#include <cuda_runtime.h>
#include <cuda_bf16.h>
#include <mma.h>
#include <stdint.h>
#include <math.h>

using namespace nvcuda;

#define NA   8000
#define NRES 2000
#define KNN_K 15
#define NE   (NA*KNN_K)        // 120000
#define NANG 9998
#define EPAD (938*128)         // 120064 padded edge rows
#define APAD (79*128)          // 10112 padded angle rows
#define PPAD (63*128)          // 8064 padded atom rows
#define NTILE_E 938
#define NTILE_A 79
#define SP  136                // smem bf16 row stride (pad, mult of 8)
#define SPF 20                 // float scratch row stride (mult of 4)

typedef unsigned long long ull;
typedef unsigned int u32;

__device__ __forceinline__ float fast_tanh(float x) {
    float y; asm("tanh.approx.f32 %0, %1;" : "=f"(y) : "f"(x)); return y;
}

// ---------------------------------------------------------------------------
// scratch
// ---------------------------------------------------------------------------
__device__ float g_coords[NA*3];
__device__ float g_vels[NA*3];
__device__ float g_accs[NA*3];
__device__ float g_tf[NA*3];
__device__ float g_aacc[NA*3];
__device__ int   g_nbr[NE];
__device__ float g_nd[NE*3];
__device__ float g_P[PPAD*128];
__device__ float g_Q[PPAD*128];
__device__ float g_A1[PPAD*128];
__device__ float g_AF[NANG];
__device__ float g_geom[NANG*8];
__device__ __align__(16) __nv_bfloat16 g_H1b[(size_t)NTILE_E*128*128];  // row-major tiles
__device__ __align__(16) __nv_bfloat16 g_G1b[(size_t)NTILE_A*128*128];
__device__ __align__(16) __nv_bfloat16 g_W2b[128*128];   // [k][n] row-major bf16
__device__ __align__(16) __nv_bfloat16 g_W3b[128*128];
__device__ __align__(16) __nv_bfloat16 g_aW2b[128*128];

// ---------------------------------------------------------------------------
// init / loss / integration
// ---------------------------------------------------------------------------
__global__ void init_kernel(const float* __restrict__ coords,
                            const float* __restrict__ vels,
                            const float* __restrict__ temp) {
    int i = blockIdx.x*blockDim.x + threadIdx.x;
    if (i >= NA*3) return;
    g_coords[i] = coords[i];
    g_vels[i]   = vels[i] * temp[0];
    g_accs[i]   = 0.0f;
}

__global__ void loss_kernel(const float* __restrict__ coords,
                            const float* __restrict__ vels,
                            const float* __restrict__ temp,
                            const float* __restrict__ dtp,
                            float* __restrict__ out_loss) {
    __shared__ float red[256];
    float T = temp[0], dt = dtp[0];
    float s = 0.0f;
    for (int i = threadIdx.x; i < NA*3; i += 256) {
        float c = coords[i];
        float x = ((vels[i]*T)*dt)*3.0f;
        float r = (c + x) - c;
        s += r*r;
    }
    red[threadIdx.x] = s; __syncthreads();
    for (int o = 128; o > 0; o >>= 1) {
        if (threadIdx.x < o) red[threadIdx.x] += red[threadIdx.x+o];
        __syncthreads();
    }
    if (threadIdx.x == 0) out_loss[0] = sqrtf(red[0] / (float)NA);
}

__global__ void pos_update_kernel(const float* __restrict__ dtp) {
    int i = blockIdx.x*blockDim.x + threadIdx.x;
    if (i >= NA*3) return;
    float dt = dtp[0];
    g_coords[i] = g_coords[i] + g_vels[i]*dt + 0.5f*g_accs[i]*dt*dt;
    g_aacc[i] = 0.0f;
    g_tf[i]   = 0.0f;
}

__global__ void finalize_kernel(const float* __restrict__ masses,
                                const float* __restrict__ dtp) {
    int i = blockIdx.x*blockDim.x + threadIdx.x;
    if (i >= NA) return;
    float m = masses[i], dt = dtp[0];
#pragma unroll
    for (int d = 0; d < 3; ++d) {
        float tf  = g_tf[i*3+d] / 100.0f;
        float acc = tf / m + g_aacc[i*3+d] / (m*100.0f);
        float al  = g_accs[i*3+d];
        g_vels[i*3+d] += 0.5f*(al + acc)*dt;
        g_accs[i*3+d]  = acc;
    }
}

__global__ void writeout_kernel(float* __restrict__ out) {
    int i = blockIdx.x*blockDim.x + threadIdx.x;
    if (i < NA*3) out[i] = g_coords[i];
}

// ---------------------------------------------------------------------------
// KNN (proven correct)
// ---------------------------------------------------------------------------
__global__ void knn_kernel() {
    __shared__ float4 chunk[1024];
    __shared__ ull    lists[8][32][16];
    int tid  = threadIdx.x;
    int widx = tid >> 5, lane = tid & 31;
    int q = blockIdx.x*8 + widx;
    float qx = g_coords[q*3+0], qy = g_coords[q*3+1], qz = g_coords[q*3+2];

    ull best[16];
#pragma unroll
    for (int t = 0; t < 16; ++t) best[t] = ~0ull;

    for (int base = 0; base < NA; base += 1024) {
        int n = min(1024, NA - base);
        __syncthreads();
        for (int t = tid; t < n; t += 256)
            chunk[t] = make_float4(g_coords[(base+t)*3+0],
                                   g_coords[(base+t)*3+1],
                                   g_coords[(base+t)*3+2], 0.0f);
        __syncthreads();
        for (int c = lane; c < n; c += 32) {
            float4 p = chunk[c];
            float dx = qx - p.x, dy = qy - p.y, dz = qz - p.z;
            float d2 = dx*dx + dy*dy + dz*dz;
            ull key = ((ull)__float_as_uint(d2) << 32) | (unsigned)(base + c);
            if (key < best[15]) {
                best[15] = key;
#pragma unroll
                for (int t = 15; t > 0; --t) {
                    ull a = best[t-1], b = best[t];
                    best[t-1] = (a < b) ? a : b;
                    best[t]   = (a < b) ? b : a;
                }
            }
        }
    }

    ull* ml = &lists[widx][lane][0];
#pragma unroll
    for (int t = 0; t < 16; ++t) ml[t] = best[t];

    int p = 0;
#pragma unroll 1
    for (int r = 0; r < 16; ++r) {
        ull cand = (p < 16) ? ml[p] : ~0ull;
        ull m = cand;
#pragma unroll
        for (int o = 16; o > 0; o >>= 1) {
            ull other = __shfl_xor_sync(0xffffffffu, m, o);
            m = (m < other) ? m : other;
        }
        if (cand == m) p++;
        if (lane == 0 && r > 0)
            g_nbr[q*KNN_K + (r-1)] = (int)(unsigned)(m & 0xffffffffull);
    }
}

// ---------------------------------------------------------------------------
// weight prep: bf16 row-major copies
// ---------------------------------------------------------------------------
__global__ void prep_weights_kernel(const float* __restrict__ dW2,
                                    const float* __restrict__ dW3,
                                    const float* __restrict__ aW2) {
    int idx0 = blockIdx.x*blockDim.x + threadIdx.x;
    for (int idx = idx0; idx < 128*128; idx += gridDim.x*blockDim.x) {
        g_W2b[idx]  = __float2bfloat16(dW2[idx]);
        g_W3b[idx]  = __float2bfloat16(dW3[idx]);
        g_aW2b[idx] = __float2bfloat16(aW2[idx]);
    }
}

// ---------------------------------------------------------------------------
// edge layer 1 (gather) -> bf16 row-major tiles
// ---------------------------------------------------------------------------
__global__ void edge_h1_kernel(const float* __restrict__ dW1,
                               const float* __restrict__ db1) {
    int widx = threadIdx.x >> 5, lane = threadIdx.x & 31;
    int e = blockIdx.x*8 + widx;
    if (e >= EPAD) return;
    __nv_bfloat16* dst = g_H1b + (size_t)e*128 + lane*4;

    if (e >= NE) { *(uint2*)dst = make_uint2(0u, 0u); return; }

    int i = e / KNN_K;
    int j = g_nbr[e];
    float dx = g_coords[i*3+0] - g_coords[j*3+0];
    float dy = g_coords[i*3+1] - g_coords[j*3+1];
    float dz = g_coords[i*3+2] - g_coords[j*3+2];
    float dist = sqrtf(dx*dx + dy*dy + dz*dz);
    float inv = 1.0f / fmaxf(dist, 0.01f);
    if (lane == 0) {
        g_nd[e*3+0] = dx*inv; g_nd[e*3+1] = dy*inv; g_nd[e*3+2] = dz*inv;
    }
    float seq = fminf(fabsf((float)(i >> 2) - (float)(j >> 2)) / 5.0f, 1.0f);

    int n0 = lane*4;
    float4 pp  = *(const float4*)&g_P[i*128 + n0];
    float4 qq  = *(const float4*)&g_Q[j*128 + n0];
    float4 w48 = *(const float4*)&dW1[48*128 + n0];
    float4 w49 = *(const float4*)&dW1[49*128 + n0];
    float4 b   = *(const float4*)&db1[n0];
    float h0 = fast_tanh(pp.x + qq.x + dist*w48.x + seq*w49.x + b.x);
    float h1 = fast_tanh(pp.y + qq.y + dist*w48.y + seq*w49.y + b.y);
    float h2 = fast_tanh(pp.z + qq.z + dist*w48.z + seq*w49.z + b.z);
    float h3 = fast_tanh(pp.w + qq.w + dist*w48.w + seq*w49.w + b.w);
    __nv_bfloat162 p0 = __floats2bfloat162_rn(h0, h1);
    __nv_bfloat162 p1 = __floats2bfloat162_rn(h2, h3);
    uint2 v; v.x = *(u32*)&p0; v.y = *(u32*)&p1;
    *(uint2*)dst = v;
}

// ---------------------------------------------------------------------------
// fused dist MLP (wmma bf16): tile -> W2 -> tanh -> W3 -> tanh -> .W4 -> atomics
// 256 threads (8 warps); each warp owns a 16-row stripe; stripe-local H reuse.
// ---------------------------------------------------------------------------
#define SM_DIST (34816*3 + 10240)
__global__ void __launch_bounds__(256)
fused_dist_kernel(const float* __restrict__ db2, const float* __restrict__ db3,
                  const float* __restrict__ dW4, const float* __restrict__ db4) {
    extern __shared__ char sm[];
    __nv_bfloat16* sA  = (__nv_bfloat16*)sm;               // 128 x SP, also H
    __nv_bfloat16* sW2 = (__nv_bfloat16*)(sm + 34816);
    __nv_bfloat16* sW3 = (__nv_bfloat16*)(sm + 69632);
    float*         ssc = (float*)(sm + 104448);            // 8 warps x 16 x SPF
    int tid = threadIdx.x, w = tid >> 5, lane = tid & 31;

    {
        const uint4* gA  = (const uint4*)(g_H1b + (size_t)blockIdx.x*128*128);
        const uint4* gW2 = (const uint4*)g_W2b;
        const uint4* gW3 = (const uint4*)g_W3b;
        for (int i = tid; i < 2048; i += 256) {
            int row = i >> 4, c8 = i & 15;
            int d = row*SP + c8*8;
            *(uint4*)&sA[d]  = gA[i];
            *(uint4*)&sW2[d] = gW2[i];
            *(uint4*)&sW3[d] = gW3[i];
        }
    }
    __syncthreads();

    float* sc = ssc + w*(16*SPF);
    int r = lane >> 1, ch = (lane & 1)*8;

    wmma::fragment<wmma::accumulator,16,16,16,float> acc[8];

    // ---- layer 2 ----
    {
        wmma::fragment<wmma::matrix_a,16,16,16,__nv_bfloat16,wmma::row_major> af[8];
#pragma unroll
        for (int kt = 0; kt < 8; ++kt)
            wmma::load_matrix_sync(af[kt], &sA[(w*16)*SP + kt*16], SP);
#pragma unroll
        for (int f = 0; f < 8; ++f) wmma::fill_fragment(acc[f], 0.0f);
#pragma unroll
        for (int kt = 0; kt < 8; ++kt) {
#pragma unroll
            for (int f = 0; f < 8; ++f) {
                wmma::fragment<wmma::matrix_b,16,16,16,__nv_bfloat16,wmma::row_major> bf;
                wmma::load_matrix_sync(bf, &sW2[(kt*16)*SP + f*16], SP);
                wmma::mma_sync(acc[f], af[kt], bf, acc[f]);
            }
        }
    }
    // epilogue 1: tanh(+b2) -> bf16 into own stripe of sA
#pragma unroll
    for (int f = 0; f < 8; ++f) {
        wmma::store_matrix_sync(sc, acc[f], SPF, wmma::mem_row_major);
        __syncwarp();
        float v[8];
#pragma unroll
        for (int c = 0; c < 8; ++c)
            v[c] = fast_tanh(sc[r*SPF + ch + c] + db2[f*16 + ch + c]);
        __nv_bfloat162 q0 = __floats2bfloat162_rn(v[0], v[1]);
        __nv_bfloat162 q1 = __floats2bfloat162_rn(v[2], v[3]);
        __nv_bfloat162 q2 = __floats2bfloat162_rn(v[4], v[5]);
        __nv_bfloat162 q3 = __floats2bfloat162_rn(v[6], v[7]);
        uint4 pk; pk.x = *(u32*)&q0; pk.y = *(u32*)&q1; pk.z = *(u32*)&q2; pk.w = *(u32*)&q3;
        *(uint4*)&sA[(w*16 + r)*SP + f*16 + ch] = pk;
        __syncwarp();
    }

    // ---- layer 3 ----
    {
        wmma::fragment<wmma::matrix_a,16,16,16,__nv_bfloat16,wmma::row_major> af[8];
#pragma unroll
        for (int kt = 0; kt < 8; ++kt)
            wmma::load_matrix_sync(af[kt], &sA[(w*16)*SP + kt*16], SP);
#pragma unroll
        for (int f = 0; f < 8; ++f) wmma::fill_fragment(acc[f], 0.0f);
#pragma unroll
        for (int kt = 0; kt < 8; ++kt) {
#pragma unroll
            for (int f = 0; f < 8; ++f) {
                wmma::fragment<wmma::matrix_b,16,16,16,__nv_bfloat16,wmma::row_major> bf;
                wmma::load_matrix_sync(bf, &sW3[(kt*16)*SP + f*16], SP);
                wmma::mma_sync(acc[f], af[kt], bf, acc[f]);
            }
        }
    }
    // epilogue 2: s = sum_n tanh(+b3)*w4
    float s = 0.0f;
#pragma unroll
    for (int f = 0; f < 8; ++f) {
        wmma::store_matrix_sync(sc, acc[f], SPF, wmma::mem_row_major);
        __syncwarp();
#pragma unroll
        for (int c = 0; c < 8; ++c) {
            int n = f*16 + ch + c;
            s += fast_tanh(sc[r*SPF + ch + c] + db3[n]) * dW4[n];
        }
        __syncwarp();
    }
    s += __shfl_xor_sync(0xffffffffu, s, 1);

    if ((lane & 1) == 0) {
        int e = blockIdx.x*128 + w*16 + r;
        if (e < NE) {
            s += db4[0];
            int a = e / KNN_K;
            atomicAdd(&g_tf[a*3+0], s * g_nd[e*3+0]);
            atomicAdd(&g_tf[a*3+1], s * g_nd[e*3+1]);
            atomicAdd(&g_tf[a*3+2], s * g_nd[e*3+2]);
        }
    }
}

// ---------------------------------------------------------------------------
// angles
// ---------------------------------------------------------------------------
struct AngleInfo { int u1, u2, u3, ct; };
__device__ __forceinline__ AngleInfo angle_info(int inst) {
    AngleInfo ai; int r;
    if (inst < 2000)      { r = inst;       ai.u1=4*r;   ai.u2=4*r+1; ai.u3=4*r+2; ai.ct=4*r+1; }
    else if (inst < 3999) { r = inst-2000;  ai.u1=4*r+1; ai.u2=4*r+2; ai.u3=4*r+4; ai.ct=4*r+2; }
    else if (inst < 5998) { r = inst-3999;  ai.u1=4*r+2; ai.u2=4*r+4; ai.u3=4*r+5; ai.ct=4*r+4; }
    else if (inst < 7998) { r = inst-5998;  ai.u1=4*r;   ai.u2=4*r+1; ai.u3=4*r+3; ai.ct=4*r+1; }
    else                  { r = inst-7998;  ai.u1=4*r+2; ai.u2=4*r+1; ai.u3=4*r+3; ai.ct=4*r+1; }
    return ai;
}

__global__ void angle_geom_kernel(const float* __restrict__ aW1) {
    int widx = threadIdx.x >> 5, lane = threadIdx.x & 31;
    int inst = blockIdx.x*8 + widx;
    if (inst >= APAD) return;
    __nv_bfloat16* dst = g_G1b + (size_t)inst*128 + lane*4;
    if (inst >= NANG) { *(uint2*)dst = make_uint2(0u, 0u); return; }

    AngleInfo ai = angle_info(inst);
    float bax = g_coords[ai.u1*3+0] - g_coords[ai.u2*3+0];
    float bay = g_coords[ai.u1*3+1] - g_coords[ai.u2*3+1];
    float baz = g_coords[ai.u1*3+2] - g_coords[ai.u2*3+2];
    float bcx = g_coords[ai.u3*3+0] - g_coords[ai.u2*3+0];
    float bcy = g_coords[ai.u3*3+1] - g_coords[ai.u2*3+1];
    float bcz = g_coords[ai.u3*3+2] - g_coords[ai.u2*3+2];
    float ba_n = sqrtf(bax*bax + bay*bay + baz*baz);
    float bc_n = sqrtf(bcx*bcx + bcy*bcy + bcz*bcz);
    float cosang = (bax*bcx + bay*bcy + baz*bcz) / (ba_n * bc_n);
    cosang = fminf(fmaxf(cosang, -1.0f + 1e-6f), 1.0f - 1e-6f);
    float ang = acosf(cosang);
    if (lane == 0) {
        g_geom[inst*8+0]=bax; g_geom[inst*8+1]=bay; g_geom[inst*8+2]=baz;
        g_geom[inst*8+3]=bcx; g_geom[inst*8+4]=bcy; g_geom[inst*8+5]=bcz;
    }
    int n0 = lane*4;
    float4 a1 = *(const float4*)&g_A1[ai.ct*128 + n0];
    float4 w  = *(const float4*)&aW1[24*128 + n0];
    float h0 = fast_tanh(a1.x + ang*w.x);
    float h1 = fast_tanh(a1.y + ang*w.y);
    float h2 = fast_tanh(a1.z + ang*w.z);
    float h3 = fast_tanh(a1.w + ang*w.w);
    __nv_bfloat162 p0 = __floats2bfloat162_rn(h0, h1);
    __nv_bfloat162 p1 = __floats2bfloat162_rn(h2, h3);
    uint2 v; v.x = *(u32*)&p0; v.y = *(u32*)&p1;
    *(uint2*)dst = v;
}

#define SM_ANG (34816*2 + 10240)
__global__ void __launch_bounds__(256)
fused_angle_kernel(const float* __restrict__ ab2, const float* __restrict__ aW3,
                   const float* __restrict__ ab3) {
    extern __shared__ char sm[];
    __nv_bfloat16* sA = (__nv_bfloat16*)sm;
    __nv_bfloat16* sW = (__nv_bfloat16*)(sm + 34816);
    float*        ssc = (float*)(sm + 69632);
    int tid = threadIdx.x, w = tid >> 5, lane = tid & 31;

    {
        const uint4* gA = (const uint4*)(g_G1b + (size_t)blockIdx.x*128*128);
        const uint4* gW = (const uint4*)g_aW2b;
        for (int i = tid; i < 2048; i += 256) {
            int row = i >> 4, c8 = i & 15;
            int d = row*SP + c8*8;
            *(uint4*)&sA[d] = gA[i];
            *(uint4*)&sW[d] = gW[i];
        }
    }
    __syncthreads();

    float* sc = ssc + w*(16*SPF);
    int r = lane >> 1, ch = (lane & 1)*8;

    wmma::fragment<wmma::accumulator,16,16,16,float> acc[8];
    {
        wmma::fragment<wmma::matrix_a,16,16,16,__nv_bfloat16,wmma::row_major> af[8];
#pragma unroll
        for (int kt = 0; kt < 8; ++kt)
            wmma::load_matrix_sync(af[kt], &sA[(w*16)*SP + kt*16], SP);
#pragma unroll
        for (int f = 0; f < 8; ++f) wmma::fill_fragment(acc[f], 0.0f);
#pragma unroll
        for (int kt = 0; kt < 8; ++kt) {
#pragma unroll
            for (int f = 0; f < 8; ++f) {
                wmma::fragment<wmma::matrix_b,16,16,16,__nv_bfloat16,wmma::row_major> bf;
                wmma::load_matrix_sync(bf, &sW[(kt*16)*SP + f*16], SP);
                wmma::mma_sync(acc[f], af[kt], bf, acc[f]);
            }
        }
    }

    float s = 0.0f;
#pragma unroll
    for (int f = 0; f < 8; ++f) {
        wmma::store_matrix_sync(sc, acc[f], SPF, wmma::mem_row_major);
        __syncwarp();
#pragma unroll
        for (int c = 0; c < 8; ++c) {
            int n = f*16 + ch + c;
            s += fast_tanh(sc[r*SPF + ch + c] + ab2[n]) * aW3[n];
        }
        __syncwarp();
    }
    s += __shfl_xor_sync(0xffffffffu, s, 1);

    if ((lane & 1) == 0) {
        int inst = blockIdx.x*128 + w*16 + r;
        if (inst < NANG) g_AF[inst] = s + ab3[0];
    }
}

__global__ void angle_force_kernel() {
    int inst = blockIdx.x*blockDim.x + threadIdx.x;
    if (inst >= NANG) return;
    AngleInfo ai = angle_info(inst);
    float af = g_AF[inst];
    float bax=g_geom[inst*8+0], bay=g_geom[inst*8+1], baz=g_geom[inst*8+2];
    float bcx=g_geom[inst*8+3], bcy=g_geom[inst*8+4], bcz=g_geom[inst*8+5];
    float ba_n = sqrtf(bax*bax + bay*bay + baz*baz);
    float bc_n = sqrtf(bcx*bcx + bcy*bcy + bcz*bcz);
    float crx = bay*bcz - baz*bcy;
    float cry = baz*bcx - bax*bcz;
    float crz = bax*bcy - bay*bcx;
    float v1x = bay*crz - baz*cry;
    float v1y = baz*crx - bax*crz;
    float v1z = bax*cry - bay*crx;
    float n1 = fmaxf(sqrtf(v1x*v1x + v1y*v1y + v1z*v1z), 1e-12f);
    float v2x = -(bcy*crz - bcz*cry);
    float v2y = -(bcz*crx - bcx*crz);
    float v2z = -(bcx*cry - bcy*crx);
    float n2 = fmaxf(sqrtf(v2x*v2x + v2y*v2y + v2z*v2z), 1e-12f);
    float fax = af*(v1x/n1)/ba_n, fay = af*(v1y/n1)/ba_n, faz = af*(v1z/n1)/ba_n;
    float fcx = af*(v2x/n2)/bc_n, fcy = af*(v2y/n2)/bc_n, fcz = af*(v2z/n2)/bc_n;
    atomicAdd(&g_aacc[ai.u1*3+0], fax);
    atomicAdd(&g_aacc[ai.u1*3+1], fay);
    atomicAdd(&g_aacc[ai.u1*3+2], faz);
    atomicAdd(&g_aacc[ai.u2*3+0], -fax - fcx);
    atomicAdd(&g_aacc[ai.u2*3+1], -fay - fcy);
    atomicAdd(&g_aacc[ai.u2*3+2], -faz - fcz);
    atomicAdd(&g_aacc[ai.u3*3+0], fcx);
    atomicAdd(&g_aacc[ai.u3*3+1], fcy);
    atomicAdd(&g_aacc[ai.u3*3+2], fcz);
}

// ---------------------------------------------------------------------------
// fp32 GEMM for the one-time precomputes (small K)
// ---------------------------------------------------------------------------
__global__ void gemm_tanh_kernel(const float* __restrict__ A,
                                 const float* __restrict__ W,
                                 const float* __restrict__ bias,
                                 float* __restrict__ C,
                                 int M, int K, int fuse) {
    __shared__ float Ast[16][128];
    __shared__ float Ws [16][128];
    int tid = threadIdx.x;
    int tm = tid >> 4, tn = tid & 15;
    int bm = blockIdx.x * 128;

    float acc[8][8];
#pragma unroll
    for (int i = 0; i < 8; ++i)
#pragma unroll
        for (int j = 0; j < 8; ++j) acc[i][j] = 0.0f;

    int arow = tid >> 1;
    int acol = (tid & 1) * 8;
    int wrow = tid >> 4;
    int wcol = (tid & 15) * 8;

    for (int kk = 0; kk < K; kk += 16) {
        {
            int grow = bm + arow;
            float4 v0 = make_float4(0,0,0,0), v1 = make_float4(0,0,0,0);
            if (grow < M && (kk + acol) < K) {
                const float* ap = A + (size_t)grow*K + kk + acol;
                v0 = *(const float4*)ap;
                v1 = *(const float4*)(ap + 4);
            }
            Ast[acol+0][arow] = v0.x; Ast[acol+1][arow] = v0.y;
            Ast[acol+2][arow] = v0.z; Ast[acol+3][arow] = v0.w;
            Ast[acol+4][arow] = v1.x; Ast[acol+5][arow] = v1.y;
            Ast[acol+6][arow] = v1.z; Ast[acol+7][arow] = v1.w;
        }
        {
            int gk = kk + wrow;
            float4 v0 = make_float4(0,0,0,0), v1 = make_float4(0,0,0,0);
            if (gk < K) {
                const float* wp = W + (size_t)gk*128 + wcol;
                v0 = *(const float4*)wp;
                v1 = *(const float4*)(wp + 4);
            }
            *(float4*)&Ws[wrow][wcol]   = v0;
            *(float4*)&Ws[wrow][wcol+4] = v1;
        }
        __syncthreads();
#pragma unroll
        for (int k2 = 0; k2 < 16; ++k2) {
            float4 a0 = *(const float4*)&Ast[k2][tm*8];
            float4 a1 = *(const float4*)&Ast[k2][tm*8+4];
            float4 w0 = *(const float4*)&Ws[k2][tn*8];
            float4 w1 = *(const float4*)&Ws[k2][tn*8+4];
            float av[8] = {a0.x,a0.y,a0.z,a0.w,a1.x,a1.y,a1.z,a1.w};
            float wv[8] = {w0.x,w0.y,w0.z,w0.w,w1.x,w1.y,w1.z,w1.w};
#pragma unroll
            for (int i = 0; i < 8; ++i)
#pragma unroll
                for (int j = 0; j < 8; ++j)
                    acc[i][j] += av[i]*wv[j];
        }
        __syncthreads();
    }
    float bv[8];
    if (fuse >= 1) {
        float4 b0 = *(const float4*)&bias[tn*8];
        float4 b1 = *(const float4*)&bias[tn*8+4];
        bv[0]=b0.x; bv[1]=b0.y; bv[2]=b0.z; bv[3]=b0.w;
        bv[4]=b1.x; bv[5]=b1.y; bv[6]=b1.z; bv[7]=b1.w;
    }
#pragma unroll
    for (int i = 0; i < 8; ++i) {
        int m = bm + tm*8 + i;
        if (m < M) {
            float o[8];
#pragma unroll
            for (int j = 0; j < 8; ++j) {
                float v = acc[i][j];
                if (fuse >= 1) v += bv[j];
                o[j] = v;
            }
            *(float4*)&C[(size_t)m*128 + tn*8]     = make_float4(o[0],o[1],o[2],o[3]);
            *(float4*)&C[(size_t)m*128 + tn*8 + 4] = make_float4(o[4],o[5],o[6],o[7]);
        }
    }
}

// ---------------------------------------------------------------------------
// host launcher
// ---------------------------------------------------------------------------
extern "C" void kernel_launch(void* const* d_in, const int* in_sizes, int n_in,
                              void* d_out, int out_size) {
    const float* coords = (const float*)d_in[0];
    const float* node_f = (const float*)d_in[1];
    const float* masses = (const float*)d_in[3];
    const float* vels   = (const float*)d_in[4];
    const float* dW1 = (const float*)d_in[5];
    const float* db1 = (const float*)d_in[6];
    const float* dW2 = (const float*)d_in[7];
    const float* db2 = (const float*)d_in[8];
    const float* dW3 = (const float*)d_in[9];
    const float* db3 = (const float*)d_in[10];
    const float* dW4 = (const float*)d_in[11];
    const float* db4 = (const float*)d_in[12];
    const float* aW1 = (const float*)d_in[13];
    const float* ab1 = (const float*)d_in[14];
    const float* aW2 = (const float*)d_in[15];
    const float* ab2 = (const float*)d_in[16];
    const float* aW3 = (const float*)d_in[17];
    const float* ab3 = (const float*)d_in[18];
    const float* dtp  = (const float*)d_in[20];
    const float* temp = (const float*)d_in[21];
    float* out = (float*)d_out;

    cudaFuncSetAttribute(fused_dist_kernel,  cudaFuncAttributeMaxDynamicSharedMemorySize, SM_DIST);
    cudaFuncSetAttribute(fused_angle_kernel, cudaFuncAttributeMaxDynamicSharedMemorySize, SM_ANG);

    float *pP, *pQ, *pA1;
    cudaGetSymbolAddress((void**)&pP,  g_P);
    cudaGetSymbolAddress((void**)&pQ,  g_Q);
    cudaGetSymbolAddress((void**)&pA1, g_A1);

    init_kernel<<<(NA*3 + 255)/256, 256>>>(coords, vels, temp);
    loss_kernel<<<1, 256>>>(coords, vels, temp, dtp, out + (out_size - 1));

    gemm_tanh_kernel<<<63, 256>>>(node_f, dW1,          nullptr, pP,  NA, 24, 0);
    gemm_tanh_kernel<<<63, 256>>>(node_f, dW1 + 24*128, nullptr, pQ,  NA, 24, 0);
    gemm_tanh_kernel<<<63, 256>>>(node_f, aW1,          ab1,     pA1, NA, 24, 1);
    prep_weights_kernel<<<32, 256>>>(dW2, dW3, aW2);

    for (int s = 0; s < 3; ++s) {
        pos_update_kernel<<<94, 256>>>(dtp);
        if (s == 2) break;

        knn_kernel<<<1000, 256>>>();
        edge_h1_kernel<<<EPAD/8, 256>>>(dW1, db1);
        fused_dist_kernel<<<NTILE_E, 256, SM_DIST>>>(db2, db3, dW4, db4);

        angle_geom_kernel<<<APAD/8, 256>>>(aW1);
        fused_angle_kernel<<<NTILE_A, 256, SM_ANG>>>(ab2, aW3, ab3);
        angle_force_kernel<<<(NANG + 255)/256, 256>>>();

        finalize_kernel<<<(NA + 255)/256, 256>>>(masses, dtp);
    }

    writeout_kernel<<<94, 256>>>(out);
}

// round 6
// speedup vs baseline: 1.3403x; 1.0005x over previous
#include <cuda_runtime.h>
#include <cuda_bf16.h>
#include <mma.h>
#include <stdint.h>
#include <math.h>

using namespace nvcuda;

#define NA   8000
#define NRES 2000
#define KNN_K 15
#define NE   (NA*KNN_K)        // 120000
#define NANG 9998
#define EPAD (938*128)         // 120064 padded edge rows
#define APAD (79*128)          // 10112 padded angle rows
#define NTILE_E 938
#define NTILE_A 79
#define SP  136                // smem bf16 row stride
#define SPF 20                 // float scratch row stride

typedef unsigned long long ull;
typedef unsigned int u32;

__device__ __forceinline__ float fast_tanh(float x) {
    float y; asm("tanh.approx.f32 %0, %1;" : "=f"(y) : "f"(x)); return y;
}

// ---------------------------------------------------------------------------
// scratch
// ---------------------------------------------------------------------------
__device__ float g_coords[NA*3];
__device__ float g_vels[NA*3];
__device__ float g_accs[NA*3];
__device__ float g_tf[NA*3];
__device__ float g_aacc[NA*3];
__device__ int   g_nbr[NE];
__device__ float g_nd[NE*3];
__device__ float g_P[8064*128];
__device__ float g_Q[8064*128];
__device__ float g_A1[8064*128];
__device__ float g_geom[NANG*8];
__device__ __align__(16) __nv_bfloat16 g_H1b[(size_t)NTILE_E*128*128];
__device__ __align__(16) __nv_bfloat16 g_G1b[(size_t)NTILE_A*128*128];
__device__ __align__(16) __nv_bfloat16 g_W2b[128*128];
__device__ __align__(16) __nv_bfloat16 g_W3b[128*128];
__device__ __align__(16) __nv_bfloat16 g_aW2b[128*128];

// ---------------------------------------------------------------------------
// init + loss (merged: blocks 0..93 init, block 94 loss)
// ---------------------------------------------------------------------------
__global__ void init_loss_kernel(const float* __restrict__ coords,
                                 const float* __restrict__ vels,
                                 const float* __restrict__ temp,
                                 const float* __restrict__ dtp,
                                 float* __restrict__ out_loss) {
    __shared__ float red[256];
    if (blockIdx.x < 94) {
        int i = blockIdx.x*256 + threadIdx.x;
        if (i < NA*3) {
            g_coords[i] = coords[i];
            g_vels[i]   = vels[i] * temp[0];
            g_accs[i]   = 0.0f;
        }
        return;
    }
    float T = temp[0], dt = dtp[0];
    float s = 0.0f;
    for (int i = threadIdx.x; i < NA*3; i += 256) {
        float c = coords[i];
        float x = ((vels[i]*T)*dt)*3.0f;
        float r = (c + x) - c;
        s += r*r;
    }
    red[threadIdx.x] = s; __syncthreads();
    for (int o = 128; o > 0; o >>= 1) {
        if (threadIdx.x < o) red[threadIdx.x] += red[threadIdx.x+o];
        __syncthreads();
    }
    if (threadIdx.x == 0) out_loss[0] = sqrtf(red[0] / (float)NA);
}

// ---------------------------------------------------------------------------
// integration
// ---------------------------------------------------------------------------
__global__ void pos_update_kernel(const float* __restrict__ dtp) {
    int i = blockIdx.x*blockDim.x + threadIdx.x;
    if (i >= NA*3) return;
    float dt = dtp[0];
    g_coords[i] = g_coords[i] + g_vels[i]*dt + 0.5f*g_accs[i]*dt*dt;
    g_aacc[i] = 0.0f;
    g_tf[i]   = 0.0f;
}

__global__ void finalize_kernel(const float* __restrict__ masses,
                                const float* __restrict__ dtp) {
    int i = blockIdx.x*blockDim.x + threadIdx.x;
    if (i >= NA) return;
    float m = masses[i], dt = dtp[0];
#pragma unroll
    for (int d = 0; d < 3; ++d) {
        float tf  = g_tf[i*3+d] / 100.0f;
        float acc = tf / m + g_aacc[i*3+d] / (m*100.0f);
        float al  = g_accs[i*3+d];
        g_vels[i*3+d] += 0.5f*(al + acc)*dt;
        g_accs[i*3+d]  = acc;
    }
}

__global__ void writeout_kernel(float* __restrict__ out) {
    int i = blockIdx.x*blockDim.x + threadIdx.x;
    if (i < NA*3) out[i] = g_coords[i];
}

// ---------------------------------------------------------------------------
// KNN (proven correct)
// ---------------------------------------------------------------------------
__global__ void knn_kernel() {
    __shared__ float4 chunk[1024];
    __shared__ ull    lists[8][32][16];
    int tid  = threadIdx.x;
    int widx = tid >> 5, lane = tid & 31;
    int q = blockIdx.x*8 + widx;
    float qx = g_coords[q*3+0], qy = g_coords[q*3+1], qz = g_coords[q*3+2];

    ull best[16];
#pragma unroll
    for (int t = 0; t < 16; ++t) best[t] = ~0ull;

    for (int base = 0; base < NA; base += 1024) {
        int n = min(1024, NA - base);
        __syncthreads();
        for (int t = tid; t < n; t += 256)
            chunk[t] = make_float4(g_coords[(base+t)*3+0],
                                   g_coords[(base+t)*3+1],
                                   g_coords[(base+t)*3+2], 0.0f);
        __syncthreads();
        for (int c = lane; c < n; c += 32) {
            float4 p = chunk[c];
            float dx = qx - p.x, dy = qy - p.y, dz = qz - p.z;
            float d2 = dx*dx + dy*dy + dz*dz;
            ull key = ((ull)__float_as_uint(d2) << 32) | (unsigned)(base + c);
            if (key < best[15]) {
                best[15] = key;
#pragma unroll
                for (int t = 15; t > 0; --t) {
                    ull a = best[t-1], b = best[t];
                    best[t-1] = (a < b) ? a : b;
                    best[t]   = (a < b) ? b : a;
                }
            }
        }
    }

    ull* ml = &lists[widx][lane][0];
#pragma unroll
    for (int t = 0; t < 16; ++t) ml[t] = best[t];

    int p = 0;
#pragma unroll 1
    for (int r = 0; r < 16; ++r) {
        ull cand = (p < 16) ? ml[p] : ~0ull;
        ull m = cand;
#pragma unroll
        for (int o = 16; o > 0; o >>= 1) {
            ull other = __shfl_xor_sync(0xffffffffu, m, o);
            m = (m < other) ? m : other;
        }
        if (cand == m) p++;
        if (lane == 0 && r > 0)
            g_nbr[q*KNN_K + (r-1)] = (int)(unsigned)(m & 0xffffffffull);
    }
}

// ---------------------------------------------------------------------------
// one-time precompute: P/Q/A1 gemms + bf16 weight conversion (single launch)
// grid dim3(64, 3): x==63 -> weight slab y; else gemm slab y, bm = x*128
// ---------------------------------------------------------------------------
__device__ void gemm128_dev(const float* __restrict__ A,
                            const float* __restrict__ W,
                            const float* __restrict__ bias,
                            float* __restrict__ C,
                            int M, int K, int fuse, int bm) {
    __shared__ float Ast[16][128];
    __shared__ float Ws [16][128];
    int tid = threadIdx.x;
    int tm = tid >> 4, tn = tid & 15;

    float acc[8][8];
#pragma unroll
    for (int i = 0; i < 8; ++i)
#pragma unroll
        for (int j = 0; j < 8; ++j) acc[i][j] = 0.0f;

    int arow = tid >> 1;
    int acol = (tid & 1) * 8;
    int wrow = tid >> 4;
    int wcol = (tid & 15) * 8;

    for (int kk = 0; kk < K; kk += 16) {
        {
            int grow = bm + arow;
            float4 v0 = make_float4(0,0,0,0), v1 = make_float4(0,0,0,0);
            if (grow < M && (kk + acol) < K) {
                const float* ap = A + (size_t)grow*K + kk + acol;
                v0 = *(const float4*)ap;
                v1 = *(const float4*)(ap + 4);
            }
            Ast[acol+0][arow] = v0.x; Ast[acol+1][arow] = v0.y;
            Ast[acol+2][arow] = v0.z; Ast[acol+3][arow] = v0.w;
            Ast[acol+4][arow] = v1.x; Ast[acol+5][arow] = v1.y;
            Ast[acol+6][arow] = v1.z; Ast[acol+7][arow] = v1.w;
        }
        {
            int gk = kk + wrow;
            float4 v0 = make_float4(0,0,0,0), v1 = make_float4(0,0,0,0);
            if (gk < K) {
                const float* wp = W + (size_t)gk*128 + wcol;
                v0 = *(const float4*)wp;
                v1 = *(const float4*)(wp + 4);
            }
            *(float4*)&Ws[wrow][wcol]   = v0;
            *(float4*)&Ws[wrow][wcol+4] = v1;
        }
        __syncthreads();
#pragma unroll
        for (int k2 = 0; k2 < 16; ++k2) {
            float4 a0 = *(const float4*)&Ast[k2][tm*8];
            float4 a1 = *(const float4*)&Ast[k2][tm*8+4];
            float4 w0 = *(const float4*)&Ws[k2][tn*8];
            float4 w1 = *(const float4*)&Ws[k2][tn*8+4];
            float av[8] = {a0.x,a0.y,a0.z,a0.w,a1.x,a1.y,a1.z,a1.w};
            float wv[8] = {w0.x,w0.y,w0.z,w0.w,w1.x,w1.y,w1.z,w1.w};
#pragma unroll
            for (int i = 0; i < 8; ++i)
#pragma unroll
                for (int j = 0; j < 8; ++j)
                    acc[i][j] += av[i]*wv[j];
        }
        __syncthreads();
    }
    float bv[8] = {0,0,0,0,0,0,0,0};
    if (fuse >= 1) {
        float4 b0 = *(const float4*)&bias[tn*8];
        float4 b1 = *(const float4*)&bias[tn*8+4];
        bv[0]=b0.x; bv[1]=b0.y; bv[2]=b0.z; bv[3]=b0.w;
        bv[4]=b1.x; bv[5]=b1.y; bv[6]=b1.z; bv[7]=b1.w;
    }
#pragma unroll
    for (int i = 0; i < 8; ++i) {
        int m = bm + tm*8 + i;
        if (m < M) {
            float o[8];
#pragma unroll
            for (int j = 0; j < 8; ++j) o[j] = acc[i][j] + bv[j];
            *(float4*)&C[(size_t)m*128 + tn*8]     = make_float4(o[0],o[1],o[2],o[3]);
            *(float4*)&C[(size_t)m*128 + tn*8 + 4] = make_float4(o[4],o[5],o[6],o[7]);
        }
    }
}

__global__ void precompute_kernel(const float* __restrict__ node_f,
                                  const float* __restrict__ dW1,
                                  const float* __restrict__ aW1,
                                  const float* __restrict__ ab1,
                                  const float* __restrict__ dW2,
                                  const float* __restrict__ dW3,
                                  const float* __restrict__ aW2) {
    int y = blockIdx.y;
    if (blockIdx.x == 63) {
        const float* src = (y == 0) ? dW2 : (y == 1) ? dW3 : aW2;
        __nv_bfloat16* dst = (y == 0) ? g_W2b : (y == 1) ? g_W3b : g_aW2b;
        for (int idx = threadIdx.x; idx < 128*128; idx += 256)
            dst[idx] = __float2bfloat16(src[idx]);
        return;
    }
    int bm = blockIdx.x * 128;
    if (y == 0)      gemm128_dev(node_f, dW1,          nullptr, g_P,  NA, 24, 0, bm);
    else if (y == 1) gemm128_dev(node_f, dW1 + 24*128, nullptr, g_Q,  NA, 24, 0, bm);
    else             gemm128_dev(node_f, aW1,          ab1,     g_A1, NA, 24, 1, bm);
}

// ---------------------------------------------------------------------------
// edge layer 1 (gather) -> bf16 row-major tiles
// ---------------------------------------------------------------------------
__global__ void edge_h1_kernel(const float* __restrict__ dW1,
                               const float* __restrict__ db1) {
    int widx = threadIdx.x >> 5, lane = threadIdx.x & 31;
    int e = blockIdx.x*8 + widx;
    if (e >= EPAD) return;
    __nv_bfloat16* dst = g_H1b + (size_t)e*128 + lane*4;

    if (e >= NE) { *(uint2*)dst = make_uint2(0u, 0u); return; }

    int i = e / KNN_K;
    int j = g_nbr[e];
    float dx = g_coords[i*3+0] - g_coords[j*3+0];
    float dy = g_coords[i*3+1] - g_coords[j*3+1];
    float dz = g_coords[i*3+2] - g_coords[j*3+2];
    float dist = sqrtf(dx*dx + dy*dy + dz*dz);
    float inv = 1.0f / fmaxf(dist, 0.01f);
    if (lane == 0) {
        g_nd[e*3+0] = dx*inv; g_nd[e*3+1] = dy*inv; g_nd[e*3+2] = dz*inv;
    }
    float seq = fminf(fabsf((float)(i >> 2) - (float)(j >> 2)) / 5.0f, 1.0f);

    int n0 = lane*4;
    float4 pp  = *(const float4*)&g_P[i*128 + n0];
    float4 qq  = *(const float4*)&g_Q[j*128 + n0];
    float4 w48 = *(const float4*)&dW1[48*128 + n0];
    float4 w49 = *(const float4*)&dW1[49*128 + n0];
    float4 b   = *(const float4*)&db1[n0];
    float h0 = fast_tanh(pp.x + qq.x + dist*w48.x + seq*w49.x + b.x);
    float h1 = fast_tanh(pp.y + qq.y + dist*w48.y + seq*w49.y + b.y);
    float h2 = fast_tanh(pp.z + qq.z + dist*w48.z + seq*w49.z + b.z);
    float h3 = fast_tanh(pp.w + qq.w + dist*w48.w + seq*w49.w + b.w);
    __nv_bfloat162 p0 = __floats2bfloat162_rn(h0, h1);
    __nv_bfloat162 p1 = __floats2bfloat162_rn(h2, h3);
    uint2 v; v.x = *(u32*)&p0; v.y = *(u32*)&p1;
    *(uint2*)dst = v;
}

// ---------------------------------------------------------------------------
// fused dist MLP (wmma bf16, low-register form, 2 CTA/SM)
// ---------------------------------------------------------------------------
#define SM_DIST (34816*3 + 10240 + 1536)
__global__ void __launch_bounds__(256, 2)
fused_dist_kernel(const float* __restrict__ db2, const float* __restrict__ db3,
                  const float* __restrict__ dW4, const float* __restrict__ db4) {
    extern __shared__ char sm[];
    __nv_bfloat16* sA  = (__nv_bfloat16*)sm;
    __nv_bfloat16* sW2 = (__nv_bfloat16*)(sm + 34816);
    __nv_bfloat16* sW3 = (__nv_bfloat16*)(sm + 69632);
    float*         ssc = (float*)(sm + 104448);
    float*         sb2 = (float*)(sm + 114688);
    float*         sb3 = sb2 + 128;
    float*         sw4 = sb3 + 128;
    int tid = threadIdx.x, w = tid >> 5, lane = tid & 31;

    {
        const uint4* gA  = (const uint4*)(g_H1b + (size_t)blockIdx.x*16384);
        const uint4* gW2 = (const uint4*)g_W2b;
        const uint4* gW3 = (const uint4*)g_W3b;
        for (int i = tid; i < 2048; i += 256) {
            int row = i >> 4, c8 = i & 15;
            int d = row*SP + c8*8;
            *(uint4*)&sA[d]  = gA[i];
            *(uint4*)&sW2[d] = gW2[i];
            *(uint4*)&sW3[d] = gW3[i];
        }
        if (tid < 128) { sb2[tid] = db2[tid]; sb3[tid] = db3[tid]; sw4[tid] = dW4[tid]; }
    }
    __syncthreads();

    float* sc = ssc + w*(16*SPF);
    int r = lane >> 1, ch = (lane & 1)*8;

    wmma::fragment<wmma::accumulator,16,16,16,float> acc[8];

    // ---- layer 2: kt-outer, single A fragment live ----
#pragma unroll
    for (int f = 0; f < 8; ++f) wmma::fill_fragment(acc[f], 0.0f);
#pragma unroll
    for (int kt = 0; kt < 8; ++kt) {
        wmma::fragment<wmma::matrix_a,16,16,16,__nv_bfloat16,wmma::row_major> af;
        wmma::load_matrix_sync(af, &sA[(w*16)*SP + kt*16], SP);
#pragma unroll
        for (int f = 0; f < 8; ++f) {
            wmma::fragment<wmma::matrix_b,16,16,16,__nv_bfloat16,wmma::row_major> bf;
            wmma::load_matrix_sync(bf, &sW2[(kt*16)*SP + f*16], SP);
            wmma::mma_sync(acc[f], af, bf, acc[f]);
        }
    }
    // epilogue 1: tanh(+b2) -> bf16 back into own stripe of sA
#pragma unroll
    for (int f = 0; f < 8; ++f) {
        wmma::store_matrix_sync(sc, acc[f], SPF, wmma::mem_row_major);
        __syncwarp();
        float v[8];
#pragma unroll
        for (int c = 0; c < 8; ++c)
            v[c] = fast_tanh(sc[r*SPF + ch + c] + sb2[f*16 + ch + c]);
        __nv_bfloat162 q0 = __floats2bfloat162_rn(v[0], v[1]);
        __nv_bfloat162 q1 = __floats2bfloat162_rn(v[2], v[3]);
        __nv_bfloat162 q2 = __floats2bfloat162_rn(v[4], v[5]);
        __nv_bfloat162 q3 = __floats2bfloat162_rn(v[6], v[7]);
        uint4 pk; pk.x = *(u32*)&q0; pk.y = *(u32*)&q1; pk.z = *(u32*)&q2; pk.w = *(u32*)&q3;
        *(uint4*)&sA[(w*16 + r)*SP + f*16 + ch] = pk;
        __syncwarp();
    }

    // ---- layer 3 ----
#pragma unroll
    for (int f = 0; f < 8; ++f) wmma::fill_fragment(acc[f], 0.0f);
#pragma unroll
    for (int kt = 0; kt < 8; ++kt) {
        wmma::fragment<wmma::matrix_a,16,16,16,__nv_bfloat16,wmma::row_major> af;
        wmma::load_matrix_sync(af, &sA[(w*16)*SP + kt*16], SP);
#pragma unroll
        for (int f = 0; f < 8; ++f) {
            wmma::fragment<wmma::matrix_b,16,16,16,__nv_bfloat16,wmma::row_major> bf;
            wmma::load_matrix_sync(bf, &sW3[(kt*16)*SP + f*16], SP);
            wmma::mma_sync(acc[f], af, bf, acc[f]);
        }
    }
    // epilogue 2: s = sum_n tanh(+b3)*w4
    float s = 0.0f;
#pragma unroll
    for (int f = 0; f < 8; ++f) {
        wmma::store_matrix_sync(sc, acc[f], SPF, wmma::mem_row_major);
        __syncwarp();
#pragma unroll
        for (int c = 0; c < 8; ++c) {
            int n = f*16 + ch + c;
            s += fast_tanh(sc[r*SPF + ch + c] + sb3[n]) * sw4[n];
        }
        __syncwarp();
    }
    s += __shfl_xor_sync(0xffffffffu, s, 1);

    if ((lane & 1) == 0) {
        int e = blockIdx.x*128 + w*16 + r;
        if (e < NE) {
            s += db4[0];
            int a = e / KNN_K;
            atomicAdd(&g_tf[a*3+0], s * g_nd[e*3+0]);
            atomicAdd(&g_tf[a*3+1], s * g_nd[e*3+1]);
            atomicAdd(&g_tf[a*3+2], s * g_nd[e*3+2]);
        }
    }
}

// ---------------------------------------------------------------------------
// angles
// ---------------------------------------------------------------------------
struct AngleInfo { int u1, u2, u3, ct; };
__device__ __forceinline__ AngleInfo angle_info(int inst) {
    AngleInfo ai; int r;
    if (inst < 2000)      { r = inst;       ai.u1=4*r;   ai.u2=4*r+1; ai.u3=4*r+2; ai.ct=4*r+1; }
    else if (inst < 3999) { r = inst-2000;  ai.u1=4*r+1; ai.u2=4*r+2; ai.u3=4*r+4; ai.ct=4*r+2; }
    else if (inst < 5998) { r = inst-3999;  ai.u1=4*r+2; ai.u2=4*r+4; ai.u3=4*r+5; ai.ct=4*r+4; }
    else if (inst < 7998) { r = inst-5998;  ai.u1=4*r;   ai.u2=4*r+1; ai.u3=4*r+3; ai.ct=4*r+1; }
    else                  { r = inst-7998;  ai.u1=4*r+2; ai.u2=4*r+1; ai.u3=4*r+3; ai.ct=4*r+1; }
    return ai;
}

__global__ void angle_geom_kernel(const float* __restrict__ aW1) {
    int widx = threadIdx.x >> 5, lane = threadIdx.x & 31;
    int inst = blockIdx.x*8 + widx;
    if (inst >= APAD) return;
    __nv_bfloat16* dst = g_G1b + (size_t)inst*128 + lane*4;
    if (inst >= NANG) { *(uint2*)dst = make_uint2(0u, 0u); return; }

    AngleInfo ai = angle_info(inst);
    float bax = g_coords[ai.u1*3+0] - g_coords[ai.u2*3+0];
    float bay = g_coords[ai.u1*3+1] - g_coords[ai.u2*3+1];
    float baz = g_coords[ai.u1*3+2] - g_coords[ai.u2*3+2];
    float bcx = g_coords[ai.u3*3+0] - g_coords[ai.u2*3+0];
    float bcy = g_coords[ai.u3*3+1] - g_coords[ai.u2*3+1];
    float bcz = g_coords[ai.u3*3+2] - g_coords[ai.u2*3+2];
    float ba_n = sqrtf(bax*bax + bay*bay + baz*baz);
    float bc_n = sqrtf(bcx*bcx + bcy*bcy + bcz*bcz);
    float cosang = (bax*bcx + bay*bcy + baz*bcz) / (ba_n * bc_n);
    cosang = fminf(fmaxf(cosang, -1.0f + 1e-6f), 1.0f - 1e-6f);
    float ang = acosf(cosang);
    if (lane == 0) {
        g_geom[inst*8+0]=bax; g_geom[inst*8+1]=bay; g_geom[inst*8+2]=baz;
        g_geom[inst*8+3]=bcx; g_geom[inst*8+4]=bcy; g_geom[inst*8+5]=bcz;
    }
    int n0 = lane*4;
    float4 a1 = *(const float4*)&g_A1[ai.ct*128 + n0];
    float4 w  = *(const float4*)&aW1[24*128 + n0];
    float h0 = fast_tanh(a1.x + ang*w.x);
    float h1 = fast_tanh(a1.y + ang*w.y);
    float h2 = fast_tanh(a1.z + ang*w.z);
    float h3 = fast_tanh(a1.w + ang*w.w);
    __nv_bfloat162 p0 = __floats2bfloat162_rn(h0, h1);
    __nv_bfloat162 p1 = __floats2bfloat162_rn(h2, h3);
    uint2 v; v.x = *(u32*)&p0; v.y = *(u32*)&p1;
    *(uint2*)dst = v;
}

// fused angle MLP + force scatter (one launch)
#define SM_ANG (34816*2 + 10240 + 1024)
__global__ void __launch_bounds__(256, 2)
fused_angle_kernel(const float* __restrict__ ab2, const float* __restrict__ aW3,
                   const float* __restrict__ ab3) {
    extern __shared__ char sm[];
    __nv_bfloat16* sA = (__nv_bfloat16*)sm;
    __nv_bfloat16* sW = (__nv_bfloat16*)(sm + 34816);
    float*        ssc = (float*)(sm + 69632);
    float*       sab2 = (float*)(sm + 79872);
    float*       saw3 = sab2 + 128;
    int tid = threadIdx.x, w = tid >> 5, lane = tid & 31;

    {
        const uint4* gA = (const uint4*)(g_G1b + (size_t)blockIdx.x*16384);
        const uint4* gW = (const uint4*)g_aW2b;
        for (int i = tid; i < 2048; i += 256) {
            int row = i >> 4, c8 = i & 15;
            int d = row*SP + c8*8;
            *(uint4*)&sA[d] = gA[i];
            *(uint4*)&sW[d] = gW[i];
        }
        if (tid < 128) { sab2[tid] = ab2[tid]; saw3[tid] = aW3[tid]; }
    }
    __syncthreads();

    float* sc = ssc + w*(16*SPF);
    int r = lane >> 1, ch = (lane & 1)*8;

    wmma::fragment<wmma::accumulator,16,16,16,float> acc[8];
#pragma unroll
    for (int f = 0; f < 8; ++f) wmma::fill_fragment(acc[f], 0.0f);
#pragma unroll
    for (int kt = 0; kt < 8; ++kt) {
        wmma::fragment<wmma::matrix_a,16,16,16,__nv_bfloat16,wmma::row_major> af;
        wmma::load_matrix_sync(af, &sA[(w*16)*SP + kt*16], SP);
#pragma unroll
        for (int f = 0; f < 8; ++f) {
            wmma::fragment<wmma::matrix_b,16,16,16,__nv_bfloat16,wmma::row_major> bf;
            wmma::load_matrix_sync(bf, &sW[(kt*16)*SP + f*16], SP);
            wmma::mma_sync(acc[f], af, bf, acc[f]);
        }
    }

    float s = 0.0f;
#pragma unroll
    for (int f = 0; f < 8; ++f) {
        wmma::store_matrix_sync(sc, acc[f], SPF, wmma::mem_row_major);
        __syncwarp();
#pragma unroll
        for (int c = 0; c < 8; ++c) {
            int n = f*16 + ch + c;
            s += fast_tanh(sc[r*SPF + ch + c] + sab2[n]) * saw3[n];
        }
        __syncwarp();
    }
    s += __shfl_xor_sync(0xffffffffu, s, 1);

    if ((lane & 1) == 0) {
        int inst = blockIdx.x*128 + w*16 + r;
        if (inst < NANG) {
            float af_ = s + ab3[0];
            AngleInfo ai = angle_info(inst);
            float bax=g_geom[inst*8+0], bay=g_geom[inst*8+1], baz=g_geom[inst*8+2];
            float bcx=g_geom[inst*8+3], bcy=g_geom[inst*8+4], bcz=g_geom[inst*8+5];
            float ba_n = sqrtf(bax*bax + bay*bay + baz*baz);
            float bc_n = sqrtf(bcx*bcx + bcy*bcy + bcz*bcz);
            float crx = bay*bcz - baz*bcy;
            float cry = baz*bcx - bax*bcz;
            float crz = bax*bcy - bay*bcx;
            float v1x = bay*crz - baz*cry;
            float v1y = baz*crx - bax*crz;
            float v1z = bax*cry - bay*crx;
            float n1 = fmaxf(sqrtf(v1x*v1x + v1y*v1y + v1z*v1z), 1e-12f);
            float v2x = -(bcy*crz - bcz*cry);
            float v2y = -(bcz*crx - bcx*crz);
            float v2z = -(bcx*cry - bcy*crx);
            float n2 = fmaxf(sqrtf(v2x*v2x + v2y*v2y + v2z*v2z), 1e-12f);
            float fax = af_*(v1x/n1)/ba_n, fay = af_*(v1y/n1)/ba_n, faz = af_*(v1z/n1)/ba_n;
            float fcx = af_*(v2x/n2)/bc_n, fcy = af_*(v2y/n2)/bc_n, fcz = af_*(v2z/n2)/bc_n;
            atomicAdd(&g_aacc[ai.u1*3+0], fax);
            atomicAdd(&g_aacc[ai.u1*3+1], fay);
            atomicAdd(&g_aacc[ai.u1*3+2], faz);
            atomicAdd(&g_aacc[ai.u2*3+0], -fax - fcx);
            atomicAdd(&g_aacc[ai.u2*3+1], -fay - fcy);
            atomicAdd(&g_aacc[ai.u2*3+2], -faz - fcz);
            atomicAdd(&g_aacc[ai.u3*3+0], fcx);
            atomicAdd(&g_aacc[ai.u3*3+1], fcy);
            atomicAdd(&g_aacc[ai.u3*3+2], fcz);
        }
    }
}

// ---------------------------------------------------------------------------
// host launcher
// ---------------------------------------------------------------------------
extern "C" void kernel_launch(void* const* d_in, const int* in_sizes, int n_in,
                              void* d_out, int out_size) {
    const float* coords = (const float*)d_in[0];
    const float* node_f = (const float*)d_in[1];
    const float* masses = (const float*)d_in[3];
    const float* vels   = (const float*)d_in[4];
    const float* dW1 = (const float*)d_in[5];
    const float* db1 = (const float*)d_in[6];
    const float* dW2 = (const float*)d_in[7];
    const float* db2 = (const float*)d_in[8];
    const float* dW3 = (const float*)d_in[9];
    const float* db3 = (const float*)d_in[10];
    const float* dW4 = (const float*)d_in[11];
    const float* db4 = (const float*)d_in[12];
    const float* aW1 = (const float*)d_in[13];
    const float* ab1 = (const float*)d_in[14];
    const float* aW2 = (const float*)d_in[15];
    const float* ab2 = (const float*)d_in[16];
    const float* aW3 = (const float*)d_in[17];
    const float* ab3 = (const float*)d_in[18];
    const float* dtp  = (const float*)d_in[20];
    const float* temp = (const float*)d_in[21];
    float* out = (float*)d_out;

    cudaFuncSetAttribute(fused_dist_kernel,  cudaFuncAttributeMaxDynamicSharedMemorySize, SM_DIST);
    cudaFuncSetAttribute(fused_angle_kernel, cudaFuncAttributeMaxDynamicSharedMemorySize, SM_ANG);

    // launch index:                                            0
    init_loss_kernel<<<95, 256>>>(coords, vels, temp, dtp, out + (out_size - 1));
    //                                                          1
    precompute_kernel<<<dim3(64,3), 256>>>(node_f, dW1, aW1, ab1, dW2, dW3, aW2);

    for (int s = 0; s < 3; ++s) {
        pos_update_kernel<<<94, 256>>>(dtp);              // 2 (s=0)
        if (s == 2) break;

        knn_kernel<<<1000, 256>>>();                      // 3
        edge_h1_kernel<<<EPAD/8, 256>>>(dW1, db1);        // 4
        fused_dist_kernel<<<NTILE_E, 256, SM_DIST>>>(db2, db3, dW4, db4);  // 5 <- ncu
        angle_geom_kernel<<<APAD/8, 256>>>(aW1);
        fused_angle_kernel<<<NTILE_A, 256, SM_ANG>>>(ab2, aW3, ab3);
        finalize_kernel<<<32, 256>>>(masses, dtp);
    }

    writeout_kernel<<<94, 256>>>(out);
}